// round 13
// baseline (speedup 1.0000x reference)
#include <cuda_runtime.h>
#include <cuda_bf16.h>
#include <cstdint>

// Shapes
#define BB 8
#define CC 32
#define DD 64
#define HH 64
#define WW 64
#define DP 32
#define HP 32
#define WP 32
#define HID 128
#define SEQ 16
#define HW (HH*WW)
#define SPECIAL 9            // bids 0..7 = per-batch RNN, bid 8 = stats

// Scratch (device globals; no allocation allowed)
__device__ float g_pooled[BB*CC*DP*HP*WP];   // 32 MB, argmax in low 3 mantissa bits
__device__ float g_psum[BB*CC*DP];
__device__ float g_psq [BB*CC*DP];
__device__ float g_mod [BB*CC];
__device__ float g_mean[CC];
__device__ float g_g   [CC];
__device__ int   g_done;                     // == SPECIAL when scalars ready

__inline__ __device__ float warpSum(float v) {
    #pragma unroll
    for (int o = 16; o > 0; o >>= 1) v += __shfl_down_sync(0xffffffffu, v, o);
    return v;
}

__inline__ __device__ void wmax(float v, int i, float& m, int& a) {
    if (v > m) { m = v; a = i; }
}

__inline__ __device__ float packf(float m, int a) {
    return __uint_as_float((__float_as_uint(m) & ~7u) | (unsigned)a);
}

__inline__ __device__ float tanh_fast(float x) {
    const float e = __expf(2.f * x);
    return 1.f - __fdividef(2.f, e + 1.f);
}

__inline__ __device__ float dot4(float4 w, float4 h) {
    return w.x*h.x + w.y*h.y + w.z*h.z + w.w*h.w;
}

// ---------------------------------------------------------------------------
// Pass 1: maxpool 2x2x2 + packed argmax + per-plane partials.
// (43us @ 80%+ DRAM — FROZEN; adds only the 1-thread flag reset.)
// ---------------------------------------------------------------------------
__global__ void __launch_bounds__(256) k_pool(const float* __restrict__ x) {
    const int dp = blockIdx.x, c = blockIdx.y, b = blockIdx.z;
    const int tid = threadIdx.x;
    if (tid == 0 && dp == 0 && c == 0 && b == 0) g_done = 0;   // reset per replay

    const int hp = tid >> 3, q = tid & 7;
    const size_t cbase = (((size_t)b * CC + c) * DD + (size_t)(2 * dp)) * (size_t)HW;
    const int pbase = ((b * CC + c) * DP + dp) * (HP * WP);

    const float* r00 = x + cbase + (size_t)(2 * hp) * WW + 8 * q;
    const float4 a0 = __ldcs((const float4*)(r00));
    const float4 a1 = __ldcs((const float4*)(r00 + 4));
    const float4 b0 = __ldcs((const float4*)(r00 + WW));
    const float4 b1 = __ldcs((const float4*)(r00 + WW + 4));
    const float4 c0 = __ldcs((const float4*)(r00 + HW));
    const float4 c1 = __ldcs((const float4*)(r00 + HW + 4));
    const float4 d0 = __ldcs((const float4*)(r00 + HW + WW));
    const float4 d1 = __ldcs((const float4*)(r00 + HW + WW + 4));

    float m0 = a0.x; int i0 = 0;
    wmax(a0.y,1,m0,i0); wmax(b0.x,2,m0,i0); wmax(b0.y,3,m0,i0);
    wmax(c0.x,4,m0,i0); wmax(c0.y,5,m0,i0); wmax(d0.x,6,m0,i0); wmax(d0.y,7,m0,i0);
    float m1 = a0.z; int i1 = 0;
    wmax(a0.w,1,m1,i1); wmax(b0.z,2,m1,i1); wmax(b0.w,3,m1,i1);
    wmax(c0.z,4,m1,i1); wmax(c0.w,5,m1,i1); wmax(d0.z,6,m1,i1); wmax(d0.w,7,m1,i1);
    float m2 = a1.x; int i2 = 0;
    wmax(a1.y,1,m2,i2); wmax(b1.x,2,m2,i2); wmax(b1.y,3,m2,i2);
    wmax(c1.x,4,m2,i2); wmax(c1.y,5,m2,i2); wmax(d1.x,6,m2,i2); wmax(d1.y,7,m2,i2);
    float m3 = a1.z; int i3 = 0;
    wmax(a1.w,1,m3,i3); wmax(b1.z,2,m3,i3); wmax(b1.w,3,m3,i3);
    wmax(c1.z,4,m3,i3); wmax(c1.w,5,m3,i3); wmax(d1.z,6,m3,i3); wmax(d1.w,7,m3,i3);

    *(float4*)(g_pooled + pbase + hp * 32 + 4 * q) =
        make_float4(packf(m0,i0), packf(m1,i1), packf(m2,i2), packf(m3,i3));

    float lsum = m0 + m1 + m2 + m3;
    float lsq  = m0*m0 + m1*m1 + m2*m2 + m3*m3;
    lsum = warpSum(lsum);
    lsq  = warpSum(lsq);
    __shared__ float ssum[8], ssq[8];
    if ((tid & 31) == 0) { ssum[tid >> 5] = lsum; ssq[tid >> 5] = lsq; }
    __syncthreads();
    if (tid == 0) {
        float s = 0.f, qq = 0.f;
        #pragma unroll
        for (int w = 0; w < 8; w++) { s += ssum[w]; qq += ssq[w]; }
        const int bl = (b * CC + c) * DP + dp;
        g_psum[bl] = s;
        g_psq[bl]  = qq;
    }
}

// ---------------------------------------------------------------------------
// Pass 2 (fused tail): SPECIAL + 8192 one-shot scatter blocks.
//  - launch_bounds(256,7): regs <=36 so RNN path can't poison scatter occ
//    (R10 failure). One tile per block: no load-after-store serialization
//    (R11 failure).
//  - scatter blocks: front-batch 4 loads, write ALL zero-chunks (frozen
//    16x float2 pattern, independent of RNN), THEN poll flag and drop 4
//    scalar pm stores into their own freshly-dirtied L2 lines.
//  - RNN (bids 0..7) + stats (bid 8) dispatched first, fully hidden.
// ---------------------------------------------------------------------------
__global__ void __launch_bounds__(256, 7) k_tail(float* __restrict__ out,
    const float* __restrict__ W_init, const float* __restrict__ b_init,
    const float* __restrict__ W_ih,   const float* __restrict__ b_ih,
    const float* __restrict__ W_hh,   const float* __restrict__ b_hh,
    const float* __restrict__ W_mod,  const float* __restrict__ b_mod,
    const float* __restrict__ gamma,  const float* __restrict__ beta)
{
    const int bid = blockIdx.x;
    const int tid = threadIdx.x;

    if (bid >= SPECIAL) {
        // ---------------- scatter (one tile per block) ----------------
        const int p = bid - SPECIAL;
        const int b = p >> 10, c = (p >> 5) & 31, dp = p & 31;
        const int pbase = p * (HP * WP);
        const size_t obase = (((size_t)b * CC + c) * DD + (size_t)(2 * dp)) * (size_t)HW;

        // front-batched loads (pooled is L2-resident from k_pool)
        float pk[4];
        #pragma unroll
        for (int j = 0; j < 4; j++)
            pk[j] = g_pooled[pbase + tid + 256 * j];

        // zero fill — no RNN dependency; frozen 16x float2 store pattern
        const float2 zz = make_float2(0.f, 0.f);
        #pragma unroll
        for (int j = 0; j < 4; j++) {
            const int idx = tid + 256 * j;
            const int hp = idx >> 5, wp = idx & 31;
            float* p0 = out + obase + (size_t)(2 * hp) * WW + 2 * wp;
            *(float2*)(p0)           = zz;
            *(float2*)(p0 + WW)      = zz;
            *(float2*)(p0 + HW)      = zz;
            *(float2*)(p0 + HW + WW) = zz;
        }

        // wait for RNN + stats scalars
        if (tid == 0) {
            while (__ldcg(&g_done) < SPECIAL) __nanosleep(64);
        }
        __syncthreads();
        __threadfence();   // acquire

        const float f = 0.5f + __ldcg(g_mod + b * CC + c);   // 1 + (mod - 0.5)
        const float g = __ldcg(g_g + c);
        const float A  = g * f;
        const float Bv = (beta[c] - __ldcg(g_mean + c) * g) * f;

        // drop the 4 argmax values (4B each, into freshly-dirtied L2 lines)
        #pragma unroll
        for (int j = 0; j < 4; j++) {
            const int idx = tid + 256 * j;
            const int hp = idx >> 5, wp = idx & 31;
            const int a = __float_as_uint(pk[j]) & 7;
            const float pm = pk[j] * A + Bv;
            out[obase + (size_t)(2 * hp + ((a >> 1) & 1)) * WW
                      + (size_t)(a >> 2) * HW + 2 * wp + (a & 1)] = pm;
        }
        return;
    }

    if (bid == 8) {
        // ---------------- channel batch-stats ----------------
        __shared__ float sh_s[8][CC], sh_q2[8][CC];
        const int cc = tid & 31, part = tid >> 5;     // part = batch 0..7
        float s = 0.f, qv = 0.f;
        const float* ps = g_psum + (part * CC + cc) * DP;
        const float* p2 = g_psq  + (part * CC + cc) * DP;
        #pragma unroll
        for (int d = 0; d < DP; d++) { s += ps[d]; qv += p2[d]; }
        sh_s[part][cc] = s; sh_q2[part][cc] = qv;
        __syncthreads();
        if (tid < CC) {
            float ts = 0.f, tq = 0.f;
            #pragma unroll
            for (int p8 = 0; p8 < 8; p8++) { ts += sh_s[p8][tid]; tq += sh_q2[p8][tid]; }
            const float inv_n = 1.f / (float)(BB * DP * HP * WP);
            const float mean = ts * inv_n;
            const float var  = tq * inv_n - mean * mean;
            g_mean[tid] = mean;
            g_g[tid]    = gamma[tid] * rsqrtf(var + 1e-5f);
        }
        __syncthreads();
        if (tid == 0) { __threadfence(); atomicAdd(&g_done, 1); }
        return;
    }

    // ---------------- per-batch RNN (bid = batch 0..7) ----------------
    const int b = bid;
    __shared__ float s_seq[CC * SEQ];
    __shared__ float s_pm[CC];
    __shared__ float s_u[SEQ * HID];
    __shared__ __align__(16) float s_h[2][HID];

    if (tid < CC) {
        const float* p = g_psum + (b * CC + tid) * DP;
        float tot = 0.f;
        #pragma unroll
        for (int t = 0; t < SEQ; t++) {
            const float v = p[2 * t] + p[2 * t + 1];
            s_seq[tid * SEQ + t] = v * (1.f / 2048.f);
            tot += v;
        }
        s_pm[tid] = tot * (1.f / 32768.f);
    }
    __syncthreads();

    if (tid < HID) {
        // h0
        float e0 = 0.f, e1 = 0.f;
        const float* wr = W_init + tid * CC;
        #pragma unroll
        for (int cc = 0; cc < CC; cc += 2) {
            e0 += s_pm[cc]     * wr[cc];
            e1 += s_pm[cc + 1] * wr[cc + 1];
        }
        s_h[0][tid] = tanh_fast(b_init[tid] + e0 + e1);

        // u[t] = W_ih @ seq_t + b_ih + b_hh
        const float bias = b_ih[tid] + b_hh[tid];
        const float4* wir = (const float4*)(W_ih + tid * CC);
        #pragma unroll 1
        for (int t = 0; t < SEQ; t++) {
            float u0 = 0.f, u1 = 0.f;
            #pragma unroll
            for (int qk = 0; qk < CC/4; qk += 2) {
                const float4 w0 = wir[qk];
                const float4 w1 = wir[qk + 1];
                u0 += w0.x * s_seq[(qk*4+0)*SEQ + t] + w0.y * s_seq[(qk*4+1)*SEQ + t]
                    + w0.z * s_seq[(qk*4+2)*SEQ + t] + w0.w * s_seq[(qk*4+3)*SEQ + t];
                u1 += w1.x * s_seq[(qk*4+4)*SEQ + t] + w1.y * s_seq[(qk*4+5)*SEQ + t]
                    + w1.z * s_seq[(qk*4+6)*SEQ + t] + w1.w * s_seq[(qk*4+7)*SEQ + t];
            }
            s_u[t * HID + tid] = bias + u0 + u1;
        }
    }
    __syncthreads();

    // 16 recurrent steps; W_hh streamed from L1-warm global; 4 accumulators.
    #pragma unroll 1
    for (int t = 0; t < SEQ; t++) {
        if (tid < HID) {
            const int cur = t & 1;
            const float4* whr = (const float4*)(W_hh + tid * HID);
            const float4* hr  = (const float4*)s_h[cur];
            float a0 = 0.f, a1 = 0.f, a2 = 0.f, a3 = 0.f;
            #pragma unroll
            for (int k = 0; k < HID/4; k += 4) {
                a0 += dot4(whr[k],   hr[k]);
                a1 += dot4(whr[k+1], hr[k+1]);
                a2 += dot4(whr[k+2], hr[k+2]);
                a3 += dot4(whr[k+3], hr[k+3]);
            }
            s_h[cur ^ 1][tid] = tanh_fast(s_u[t * HID + tid] + (a0 + a1) + (a2 + a3));
        }
        __syncthreads();
    }

    if (tid < CC) {
        const float4* wr = (const float4*)(W_mod + tid * HID);
        const float4* hr = (const float4*)s_h[SEQ & 1];
        float a0 = 0.f, a1 = 0.f;
        #pragma unroll
        for (int k = 0; k < HID/4; k += 2) {
            a0 += dot4(wr[k],   hr[k]);
            a1 += dot4(wr[k+1], hr[k+1]);
        }
        g_mod[b * CC + tid] = 1.f / (1.f + __expf(-(b_mod[tid] + a0 + a1)));
    }
    __syncthreads();
    if (tid == 0) { __threadfence(); atomicAdd(&g_done, 1); }
}

// ---------------------------------------------------------------------------
// Launch — two kernels.
// Inputs: x, W_init, b_init, W_ih, b_ih, W_hh, b_hh, W_mod, b_mod, gamma, beta
// ---------------------------------------------------------------------------
extern "C" void kernel_launch(void* const* d_in, const int* in_sizes, int n_in,
                              void* d_out, int out_size) {
    const float* x      = (const float*)d_in[0];
    const float* W_init = (const float*)d_in[1];
    const float* b_init = (const float*)d_in[2];
    const float* W_ih   = (const float*)d_in[3];
    const float* b_ih   = (const float*)d_in[4];
    const float* W_hh   = (const float*)d_in[5];
    const float* b_hh   = (const float*)d_in[6];
    const float* W_mod  = (const float*)d_in[7];
    const float* b_mod  = (const float*)d_in[8];
    const float* gamma  = (const float*)d_in[9];
    const float* beta   = (const float*)d_in[10];
    float* out = (float*)d_out;

    dim3 grid(DP, CC, BB);
    k_pool<<<grid, 256>>>(x);
    k_tail<<<BB*CC*DP + SPECIAL, 256>>>(out, W_init, b_init, W_ih, b_ih,
                                        W_hh, b_hh, W_mod, b_mod, gamma, beta);
}

// round 14
// speedup vs baseline: 1.5251x; 1.5251x over previous
#include <cuda_runtime.h>
#include <cuda_fp16.h>
#include <cstdint>

// Shapes
#define BB 8
#define CC 32
#define DD 64
#define HH 64
#define WW 64
#define DP 32
#define HP 32
#define WP 32
#define HID 128
#define SEQ 16
#define HW (HH*WW)

// Scratch (device globals; no allocation allowed)
__device__ __half        g_pooled[BB*CC*DP*HP*WP];   // 16 MB fp16 pooled maxima
__device__ unsigned char g_amax  [BB*CC*DP*HP*WP];   // 8 MB window argmax
__device__ float g_psum[BB*CC*DP];
__device__ float g_psq [BB*CC*DP];
__device__ float g_mod [BB*CC];
__device__ float g_mean[CC];
__device__ float g_g   [CC];

__inline__ __device__ float warpSum(float v) {
    #pragma unroll
    for (int o = 16; o > 0; o >>= 1) v += __shfl_down_sync(0xffffffffu, v, o);
    return v;
}

__inline__ __device__ void wmax(float v, int i, float& m, int& a) {
    if (v > m) { m = v; a = i; }
}

__inline__ __device__ float tanh_fast(float x) {
    const float e = __expf(2.f * x);
    return 1.f - __fdividef(2.f, e + 1.f);
}

__inline__ __device__ float dot4(float4 w, float4 h) {
    return w.x*h.x + w.y*h.y + w.z*h.z + w.w*h.w;
}

// ---------------------------------------------------------------------------
// Pass 1: maxpool 2x2x2 + argmax + per-plane sum/sumsq partials.
// Load side FROZEN (43us @ 80%+ DRAM). Store side: fp16 values (8B/thread,
// 256B contiguous per warp) + uchar4 argmax (R2's measured-good pattern).
// Stats partials computed from UNQUANTIZED fp32 maxima.
// ---------------------------------------------------------------------------
__global__ void __launch_bounds__(256) k_pool(const float* __restrict__ x) {
    const int dp = blockIdx.x, c = blockIdx.y, b = blockIdx.z;
    const int tid = threadIdx.x;
    const int hp = tid >> 3, q = tid & 7;
    const size_t cbase = (((size_t)b * CC + c) * DD + (size_t)(2 * dp)) * (size_t)HW;
    const int pbase = ((b * CC + c) * DP + dp) * (HP * WP);

    const float* r00 = x + cbase + (size_t)(2 * hp) * WW + 8 * q;
    const float4 a0 = __ldcs((const float4*)(r00));
    const float4 a1 = __ldcs((const float4*)(r00 + 4));
    const float4 b0 = __ldcs((const float4*)(r00 + WW));
    const float4 b1 = __ldcs((const float4*)(r00 + WW + 4));
    const float4 c0 = __ldcs((const float4*)(r00 + HW));
    const float4 c1 = __ldcs((const float4*)(r00 + HW + 4));
    const float4 d0 = __ldcs((const float4*)(r00 + HW + WW));
    const float4 d1 = __ldcs((const float4*)(r00 + HW + WW + 4));

    float m0 = a0.x; int i0 = 0;
    wmax(a0.y,1,m0,i0); wmax(b0.x,2,m0,i0); wmax(b0.y,3,m0,i0);
    wmax(c0.x,4,m0,i0); wmax(c0.y,5,m0,i0); wmax(d0.x,6,m0,i0); wmax(d0.y,7,m0,i0);
    float m1 = a0.z; int i1 = 0;
    wmax(a0.w,1,m1,i1); wmax(b0.z,2,m1,i1); wmax(b0.w,3,m1,i1);
    wmax(c0.z,4,m1,i1); wmax(c0.w,5,m1,i1); wmax(d0.z,6,m1,i1); wmax(d0.w,7,m1,i1);
    float m2 = a1.x; int i2 = 0;
    wmax(a1.y,1,m2,i2); wmax(b1.x,2,m2,i2); wmax(b1.y,3,m2,i2);
    wmax(c1.x,4,m2,i2); wmax(c1.y,5,m2,i2); wmax(d1.x,6,m2,i2); wmax(d1.y,7,m2,i2);
    float m3 = a1.z; int i3 = 0;
    wmax(a1.w,1,m3,i3); wmax(b1.z,2,m3,i3); wmax(b1.w,3,m3,i3);
    wmax(c1.z,4,m3,i3); wmax(c1.w,5,m3,i3); wmax(d1.z,6,m3,i3); wmax(d1.w,7,m3,i3);

    const int pidx = pbase + hp * 32 + 4 * q;
    // two half2 = one 8B store, 256B contiguous per warp
    __half2 h01 = __floats2half2_rn(m0, m1);
    __half2 h23 = __floats2half2_rn(m2, m3);
    *(uint2*)(g_pooled + pidx) =
        make_uint2(*(unsigned*)&h01, *(unsigned*)&h23);
    uchar4 am; am.x = (unsigned char)i0; am.y = (unsigned char)i1;
              am.z = (unsigned char)i2; am.w = (unsigned char)i3;
    *(uchar4*)(g_amax + pidx) = am;

    float lsum = m0 + m1 + m2 + m3;
    float lsq  = m0*m0 + m1*m1 + m2*m2 + m3*m3;
    lsum = warpSum(lsum);
    lsq  = warpSum(lsq);
    __shared__ float ssum[8], ssq[8];
    if ((tid & 31) == 0) { ssum[tid >> 5] = lsum; ssq[tid >> 5] = lsq; }
    __syncthreads();
    if (tid == 0) {
        float s = 0.f, qq = 0.f;
        #pragma unroll
        for (int w = 0; w < 8; w++) { s += ssum[w]; qq += ssq[w]; }
        const int bl = (b * CC + c) * DP + dp;
        g_psum[bl] = s;
        g_psq[bl]  = qq;
    }
}

// ---------------------------------------------------------------------------
// Pass 2: per-batch RNN (blocks 0..7) + channel stats (block 8)
// (R12 checkpoint version — unchanged.)
// ---------------------------------------------------------------------------
__global__ void __launch_bounds__(128, 1) k_rnn(
    const float* __restrict__ W_init, const float* __restrict__ b_init,
    const float* __restrict__ W_ih,   const float* __restrict__ b_ih,
    const float* __restrict__ W_hh,   const float* __restrict__ b_hh,
    const float* __restrict__ W_mod,  const float* __restrict__ b_mod,
    const float* __restrict__ gamma)
{
    const int blk = blockIdx.x;
    const int tid = threadIdx.x;

    if (blk == 8) {
        __shared__ float sh_s[4][CC], sh_q[4][CC];
        const int c = tid & 31, part = tid >> 5;
        float s = 0.f, qv = 0.f;
        #pragma unroll
        for (int bi = 0; bi < 2; bi++) {
            const int b = part * 2 + bi;
            const float* p  = g_psum + (b * CC + c) * DP;
            const float* p2 = g_psq  + (b * CC + c) * DP;
            #pragma unroll
            for (int dp = 0; dp < DP; dp++) { s += p[dp]; qv += p2[dp]; }
        }
        sh_s[part][c] = s; sh_q[part][c] = qv;
        __syncthreads();
        if (tid < CC) {
            float ts = 0.f, tq = 0.f;
            #pragma unroll
            for (int p = 0; p < 4; p++) { ts += sh_s[p][tid]; tq += sh_q[p][tid]; }
            const float inv_n = 1.f / (float)(BB * DP * HP * WP);
            const float mean = ts * inv_n;
            const float var  = tq * inv_n - mean * mean;
            g_mean[tid] = mean;
            g_g[tid]    = gamma[tid] * rsqrtf(var + 1e-5f);
        }
        return;
    }

    const int b = blk;
    __shared__ float s_seq[CC * SEQ];
    __shared__ float s_pm[CC];
    __shared__ float s_u[SEQ * HID];
    __shared__ __align__(16) float s_h[2][HID];

    if (tid < CC) {
        const int c = tid;
        const float* p = g_psum + (b * CC + c) * DP;
        float tot = 0.f;
        #pragma unroll
        for (int t = 0; t < SEQ; t++) {
            const float v = p[2 * t] + p[2 * t + 1];
            s_seq[c * SEQ + t] = v * (1.f / 2048.f);
            tot += v;
        }
        s_pm[c] = tot * (1.f / 32768.f);
    }
    __syncthreads();

    {
        float e0 = 0.f, e1 = 0.f;
        const float* wr = W_init + tid * CC;
        #pragma unroll
        for (int c = 0; c < CC; c += 2) {
            e0 += s_pm[c]     * wr[c];
            e1 += s_pm[c + 1] * wr[c + 1];
        }
        s_h[0][tid] = tanh_fast(b_init[tid] + e0 + e1);
    }

    {
        const float bias = b_ih[tid] + b_hh[tid];
        const float4* wir = (const float4*)(W_ih + tid * CC);
        for (int t = 0; t < SEQ; t++) {
            float u0 = 0.f, u1 = 0.f;
            #pragma unroll
            for (int qk = 0; qk < CC/4; qk += 2) {
                const float4 w0 = wir[qk];
                const float4 w1 = wir[qk + 1];
                u0 += w0.x * s_seq[(qk*4+0)*SEQ + t] + w0.y * s_seq[(qk*4+1)*SEQ + t]
                    + w0.z * s_seq[(qk*4+2)*SEQ + t] + w0.w * s_seq[(qk*4+3)*SEQ + t];
                u1 += w1.x * s_seq[(qk*4+4)*SEQ + t] + w1.y * s_seq[(qk*4+5)*SEQ + t]
                    + w1.z * s_seq[(qk*4+6)*SEQ + t] + w1.w * s_seq[(qk*4+7)*SEQ + t];
            }
            s_u[t * HID + tid] = bias + u0 + u1;
        }
    }

    float4 wreg[HID/4];
    {
        const float4* whr = (const float4*)(W_hh + tid * HID);
        #pragma unroll
        for (int k = 0; k < HID/4; k++) wreg[k] = whr[k];
    }
    __syncthreads();

    #pragma unroll 1
    for (int t = 0; t < SEQ; t++) {
        const int cur = t & 1;
        const float4* hr = (const float4*)s_h[cur];
        float a0 = 0.f, a1 = 0.f, a2 = 0.f, a3 = 0.f;
        #pragma unroll
        for (int k = 0; k < HID/4; k += 4) {
            a0 += dot4(wreg[k],   hr[k]);
            a1 += dot4(wreg[k+1], hr[k+1]);
            a2 += dot4(wreg[k+2], hr[k+2]);
            a3 += dot4(wreg[k+3], hr[k+3]);
        }
        s_h[cur ^ 1][tid] = tanh_fast(s_u[t * HID + tid] + (a0 + a1) + (a2 + a3));
        __syncthreads();
    }

    if (tid < CC) {
        const float4* wr = (const float4*)(W_mod + tid * HID);
        const float4* hr = (const float4*)s_h[SEQ & 1];
        float a0 = 0.f, a1 = 0.f;
        #pragma unroll
        for (int k = 0; k < HID/4; k += 2) {
            a0 += dot4(wr[k],   hr[k]);
            a1 += dot4(wr[k+1], hr[k+1]);
        }
        const float acc = b_mod[tid] + a0 + a1;
        g_mod[b * CC + tid] = 1.f / (1.f + __expf(-acc));
    }
}

// ---------------------------------------------------------------------------
// Pass 3: unpool-scatter — frozen 16x float2 store pattern; reads fp16
// pooled + u8 argmax (front-batched). 24MB read instead of 32MB.
// ---------------------------------------------------------------------------
__global__ void __launch_bounds__(256) k_scatter(float* __restrict__ out,
                                                 const float* __restrict__ beta) {
    const int dp = blockIdx.x, c = blockIdx.y, b = blockIdx.z;
    const int tid = threadIdx.x;

    const float f = 0.5f + g_mod[b * CC + c];   // 1 + (mod - 0.5)
    const float g = g_g[c];
    const float A  = g * f;
    const float Bv = (beta[c] - g_mean[c] * g) * f;

    const int pbase = ((b * CC + c) * DP + dp) * (HP * WP);
    const size_t obase = (((size_t)b * CC + c) * DD + (size_t)(2 * dp)) * (size_t)HW;

    // front-batched independent loads (L2-resident from pool)
    float pk[4];
    int   av[4];
    #pragma unroll
    for (int j = 0; j < 4; j++)
        pk[j] = __half2float(g_pooled[pbase + tid + 256 * j]);
    #pragma unroll
    for (int j = 0; j < 4; j++)
        av[j] = (int)g_amax[pbase + tid + 256 * j];

    #pragma unroll
    for (int j = 0; j < 4; j++) {
        const int idx = tid + 256 * j;          // 0..1023, linear window index
        const int hp = idx >> 5, wp = idx & 31;
        const int a = av[j];
        const float pm = pk[j] * A + Bv;
        float* p0 = out + obase + (size_t)(2 * hp) * WW + 2 * wp;
        float2 z0, z1, z2, z3;
        z0.x = (a == 0) ? pm : 0.f;  z0.y = (a == 1) ? pm : 0.f;
        z1.x = (a == 2) ? pm : 0.f;  z1.y = (a == 3) ? pm : 0.f;
        z2.x = (a == 4) ? pm : 0.f;  z2.y = (a == 5) ? pm : 0.f;
        z3.x = (a == 6) ? pm : 0.f;  z3.y = (a == 7) ? pm : 0.f;
        *(float2*)(p0)                = z0;
        *(float2*)(p0 + WW)           = z1;
        *(float2*)(p0 + HW)           = z2;
        *(float2*)(p0 + HW + WW)      = z3;
    }
}

// ---------------------------------------------------------------------------
// Launch
// Inputs: x, W_init, b_init, W_ih, b_ih, W_hh, b_hh, W_mod, b_mod, gamma, beta
// ---------------------------------------------------------------------------
extern "C" void kernel_launch(void* const* d_in, const int* in_sizes, int n_in,
                              void* d_out, int out_size) {
    const float* x      = (const float*)d_in[0];
    const float* W_init = (const float*)d_in[1];
    const float* b_init = (const float*)d_in[2];
    const float* W_ih   = (const float*)d_in[3];
    const float* b_ih   = (const float*)d_in[4];
    const float* W_hh   = (const float*)d_in[5];
    const float* b_hh   = (const float*)d_in[6];
    const float* W_mod  = (const float*)d_in[7];
    const float* b_mod  = (const float*)d_in[8];
    const float* gamma  = (const float*)d_in[9];
    const float* beta   = (const float*)d_in[10];
    float* out = (float*)d_out;

    dim3 grid(DP, CC, BB);
    k_pool<<<grid, 256>>>(x);
    k_rnn<<<9, 128>>>(W_init, b_init, W_ih, b_ih, W_hh, b_hh, W_mod, b_mod, gamma);
    k_scatter<<<grid, 256>>>(out, beta);
}